// round 1
// baseline (speedup 1.0000x reference)
#include <cuda_runtime.h>

// Problem constants
#define SS 4096
#define BB 8
#define EE 1024
#define HH 16
#define DD 64
#define PP 64

// Derived
#define M_ROWS (SS * BB)        // 32768
#define N_FUSED (3 * EE)        // 3072

// ---------------- Scratch (static device globals; no allocation) -------------
__device__ float g_Wc[(size_t)N_FUSED * EE];            // combined weights 3072x1024 (12MB)
__device__ float g_fused[(size_t)M_ROWS * N_FUSED];     // q'|k'|v  (402MB)
__device__ float g_attn[(size_t)M_ROWS * EE];           // attn in (S,B,E) layout (128MB)
__device__ float g_kv[(size_t)HH * BB * PP * DD];       // 128 x 64 x 64 (2MB)
__device__ float g_ksum[(size_t)HH * BB * PP];          // 128 x 64

// ---------------- Kernel A: build combined weights ---------------------------
// Wc[n][e]:
//   n in [0,1024):    sum_d w_f[p][d] * w_qkv[h*64+d][e]          (q path)
//   n in [1024,2048): sum_d w_f[p][d] * w_qkv[1024 + h*64+d][e]   (k path)
//   n in [2048,3072): w_qkv[n][e]                                 (v copy)
__global__ void build_wc_kernel(const float* __restrict__ w_qkv,
                                const float* __restrict__ w_f) {
    int n = blockIdx.x;
    int tid = threadIdx.x;   // 256 threads
    if (n >= 2048) {
        for (int e = tid; e < EE; e += 256)
            g_Wc[(size_t)n * EE + e] = w_qkv[(size_t)n * EE + e];
        return;
    }
    int part = n >> 10;            // 0=q, 1=k
    int h = (n & 1023) >> 6;
    int p = n & 63;
    __shared__ float wf[64];
    if (tid < 64) wf[tid] = w_f[p * 64 + tid];
    __syncthreads();
    float acc[4] = {0.f, 0.f, 0.f, 0.f};
    const float* src = w_qkv + (size_t)(part * 1024 + h * 64) * EE;
#pragma unroll 4
    for (int d = 0; d < 64; d++) {
        float w = wf[d];
#pragma unroll
        for (int i = 0; i < 4; i++)
            acc[i] += w * src[(size_t)d * EE + tid + i * 256];
    }
#pragma unroll
    for (int i = 0; i < 4; i++)
        g_Wc[(size_t)n * EE + tid + i * 256] = acc[i];
}

// ---------------- SGEMM: C[M,N] = A[M,K] * Bmat[N,K]^T + epilogue ------------
// 128x128 block tile, BK=16, 256 threads, 8x8 per thread (split 4+4 at +64).
// EPI 0: plain  EPI 1: fused-qkv (n<2048 -> relu(v + bias[n&63]))  EPI 2: +bias[n]
template <int EPI>
__global__ void __launch_bounds__(256, 2)
sgemm_kernel(const float* __restrict__ A, const float* __restrict__ Bmat,
             float* __restrict__ C, int M, int N, int K,
             const float* __restrict__ bias) {
    __shared__ float As[16][128];
    __shared__ float Bs[16][128];
    int tid = threadIdx.x;
    int m0 = blockIdx.y * 128;
    int n0 = blockIdx.x * 128;

    int lr = tid >> 2;            // 0..63
    int lc = (tid & 3) * 4;       // 0,4,8,12

    int ty = tid >> 4;            // 0..15
    int tx = tid & 15;            // 0..15

    float acc[8][8];
#pragma unroll
    for (int i = 0; i < 8; i++)
#pragma unroll
        for (int j = 0; j < 8; j++) acc[i][j] = 0.f;

    const float* Aptr = A + (size_t)m0 * K;
    const float* Bptr = Bmat + (size_t)n0 * K;

    for (int k0 = 0; k0 < K; k0 += 16) {
#pragma unroll
        for (int hh = 0; hh < 2; hh++) {
            int m = lr + hh * 64;
            float4 v = *(const float4*)(Aptr + (size_t)m * K + k0 + lc);
            As[lc + 0][m] = v.x; As[lc + 1][m] = v.y;
            As[lc + 2][m] = v.z; As[lc + 3][m] = v.w;
        }
#pragma unroll
        for (int hh = 0; hh < 2; hh++) {
            int n = lr + hh * 64;
            float4 v = *(const float4*)(Bptr + (size_t)n * K + k0 + lc);
            Bs[lc + 0][n] = v.x; Bs[lc + 1][n] = v.y;
            Bs[lc + 2][n] = v.z; Bs[lc + 3][n] = v.w;
        }
        __syncthreads();
#pragma unroll
        for (int k = 0; k < 16; k++) {
            float a[8], b[8];
            float4 a0 = *(const float4*)&As[k][ty * 4];
            float4 a1 = *(const float4*)&As[k][64 + ty * 4];
            a[0] = a0.x; a[1] = a0.y; a[2] = a0.z; a[3] = a0.w;
            a[4] = a1.x; a[5] = a1.y; a[6] = a1.z; a[7] = a1.w;
            float4 b0 = *(const float4*)&Bs[k][tx * 4];
            float4 b1 = *(const float4*)&Bs[k][64 + tx * 4];
            b[0] = b0.x; b[1] = b0.y; b[2] = b0.z; b[3] = b0.w;
            b[4] = b1.x; b[5] = b1.y; b[6] = b1.z; b[7] = b1.w;
#pragma unroll
            for (int i = 0; i < 8; i++)
#pragma unroll
                for (int j = 0; j < 8; j++)
                    acc[i][j] += a[i] * b[j];
        }
        __syncthreads();
    }

    // Epilogue + store (vectorized float4 along n)
#pragma unroll
    for (int hi = 0; hi < 2; hi++) {
#pragma unroll
        for (int i = 0; i < 4; i++) {
            int m = m0 + hi * 64 + ty * 4 + i;
            float* crow = C + (size_t)m * N + n0;
#pragma unroll
            for (int hj = 0; hj < 2; hj++) {
                int ncol = hj * 64 + tx * 4;
                float4 v;
                float r[4];
#pragma unroll
                for (int j = 0; j < 4; j++) {
                    float val = acc[hi * 4 + i][hj * 4 + j];
                    int n = n0 + ncol + j;
                    if (EPI == 1) {
                        if (n < 2048) val = fmaxf(val + bias[n & 63], 0.f);
                    } else if (EPI == 2) {
                        val += bias[n];
                    }
                    r[j] = val;
                }
                v.x = r[0]; v.y = r[1]; v.z = r[2]; v.w = r[3];
                *(float4*)(crow + ncol) = v;
            }
        }
    }
}

// ---------------- Zero kv / ksum ---------------------------------------------
__global__ void zero_kernel() {
    int idx = blockIdx.x * 256 + threadIdx.x;
    const int NKV = HH * BB * PP * DD;   // 524288
    if (idx < NKV) g_kv[idx] = 0.f;
    else {
        int j = idx - NKV;
        if (j < HH * BB * PP) g_ksum[j] = 0.f;
    }
}

// ---------------- Kernel C: kv[hb][p][d] = sum_s k'[s][p]*v[s][d], ksum ------
// grid (128, 8 splits), 256 threads, 4x4 accum per thread over 64x64 output.
__global__ void __launch_bounds__(256)
kv_kernel() {
    int hb = blockIdx.x;              // h*8 + b
    int split = blockIdx.y;           // 0..7
    int h = hb >> 3, b = hb & 7;

    __shared__ float kt[64][64];
    __shared__ float vt[64][64];

    int tid = threadIdx.x;
    int c4 = tid & 15;                // float4 column group (p/d quad)
    int r0 = tid >> 4;                // 0..15 base row

    const float* kbase = g_fused + (size_t)b * N_FUSED + 1024 + h * 64;
    const float* vbase = g_fused + (size_t)b * N_FUSED + 2048 + h * 64;

    float acc[4][4];
#pragma unroll
    for (int i = 0; i < 4; i++)
#pragma unroll
        for (int j = 0; j < 4; j++) acc[i][j] = 0.f;
    float ksacc[4] = {0.f, 0.f, 0.f, 0.f};

    int ty = tid >> 4, tx = tid & 15;

    int sbeg = split * 512;
    for (int s0 = sbeg; s0 < sbeg + 512; s0 += 64) {
#pragma unroll
        for (int i = 0; i < 4; i++) {
            int row = r0 + i * 16;
            size_t g = (size_t)(s0 + row) * BB * N_FUSED;
            float4 kval = *(const float4*)(kbase + g + c4 * 4);
            *(float4*)&kt[row][c4 * 4] = kval;
            ksacc[0] += kval.x; ksacc[1] += kval.y;
            ksacc[2] += kval.z; ksacc[3] += kval.w;
            *(float4*)&vt[row][c4 * 4] = *(const float4*)(vbase + g + c4 * 4);
        }
        __syncthreads();
#pragma unroll 8
        for (int ss = 0; ss < 64; ss++) {
            float4 a = *(const float4*)&kt[ss][ty * 4];
            float4 c = *(const float4*)&vt[ss][tx * 4];
            float av[4] = {a.x, a.y, a.z, a.w};
            float cv[4] = {c.x, c.y, c.z, c.w};
#pragma unroll
            for (int i = 0; i < 4; i++)
#pragma unroll
                for (int j = 0; j < 4; j++)
                    acc[i][j] += av[i] * cv[j];
        }
        __syncthreads();
    }

    float* kvb = g_kv + (size_t)hb * (PP * DD);
#pragma unroll
    for (int i = 0; i < 4; i++)
#pragma unroll
        for (int j = 0; j < 4; j++)
            atomicAdd(&kvb[(ty * 4 + i) * 64 + tx * 4 + j], acc[i][j]);
#pragma unroll
    for (int l = 0; l < 4; l++)
        atomicAdd(&g_ksum[hb * 64 + c4 * 4 + l], ksacc[l]);
}

// ---------------- Kernel D: attn = (q' @ kv) / (q'.ksum + eps) ---------------
// grid (32 s-chunks, 128 hb), 256 threads = 4 row-groups x 64 d-lanes.
__global__ void __launch_bounds__(256)
attn_kernel() {
    int chunk = blockIdx.x;           // 0..31 (128 s each)
    int hb = blockIdx.y;
    int h = hb >> 3, b = hb & 7;

    __shared__ float kvs[64][64];
    __shared__ float kss[64];
    __shared__ float qs[4][64];

    int tid = threadIdx.x;
    for (int i = tid; i < 4096; i += 256)
        kvs[i >> 6][i & 63] = g_kv[(size_t)hb * 4096 + i];
    if (tid < 64) kss[tid] = g_ksum[hb * 64 + tid];
    __syncthreads();

    int g = tid >> 6;                 // row group 0..3
    int d = tid & 63;

    for (int it = 0; it < 32; it++) {
        int s = chunk * 128 + it * 4 + g;
        size_t row = ((size_t)s * BB + b) * N_FUSED;
        qs[g][d] = g_fused[row + h * 64 + d];   // q' columns [0,1024)
        __syncthreads();
        float num = 0.f, den = 0.f;
#pragma unroll
        for (int p = 0; p < 64; p++) {
            float q = qs[g][p];
            num += q * kvs[p][d];
            den += q * kss[p];
        }
        g_attn[((size_t)s * BB + b) * EE + h * 64 + d] = num / (den + 1e-8f);
        __syncthreads();
    }
}

// ---------------- Launch -------------------------------------------------------
extern "C" void kernel_launch(void* const* d_in, const int* in_sizes, int n_in,
                              void* d_out, int out_size) {
    const float* x      = (const float*)d_in[0];   // (S,B,E)
    const float* w_qkv  = (const float*)d_in[1];   // (3E,E)
    const float* w_out  = (const float*)d_in[2];   // (E,E)
    const float* b_out  = (const float*)d_in[3];   // (E)
    const float* w_f    = (const float*)d_in[4];   // (P,D)
    const float* b_f    = (const float*)d_in[5];   // (P)
    float* out = (float*)d_out;

    float *Wc_p, *fused_p, *attn_p;
    cudaGetSymbolAddress((void**)&Wc_p, g_Wc);
    cudaGetSymbolAddress((void**)&fused_p, g_fused);
    cudaGetSymbolAddress((void**)&attn_p, g_attn);

    // 1. combined weights
    build_wc_kernel<<<N_FUSED, 256>>>(w_qkv, w_f);

    // 2. fused qkv+featuremap GEMM: (32768 x 1024) @ (3072 x 1024)^T
    sgemm_kernel<1><<<dim3(N_FUSED / 128, M_ROWS / 128), 256>>>(
        x, Wc_p, fused_p, M_ROWS, N_FUSED, EE, b_f);

    // 3. zero accumulators
    zero_kernel<<<(HH * BB * PP * DD + HH * BB * PP + 255) / 256, 256>>>();

    // 4. kv / ksum reduction (split-S = 8)
    kv_kernel<<<dim3(HH * BB, 8), 256>>>();

    // 5. attention + normalization
    attn_kernel<<<dim3(SS / 128, HH * BB), 256>>>();

    // 6. output projection: (32768 x 1024) @ (1024 x 1024)^T + b_out
    sgemm_kernel<2><<<dim3(EE / 128, M_ROWS / 128), 256>>>(
        attn_p, w_out, out, M_ROWS, EE, EE, b_out);
}

// round 3
// speedup vs baseline: 1.8523x; 1.8523x over previous
#include <cuda_runtime.h>
#include <cuda_bf16.h>
#include <cstdint>

// Problem constants
#define SS 4096
#define BB 8
#define EE 1024
#define HH 16
#define DD 64
#define PP 64
#define M_ROWS (SS * BB)        // 32768
#define N_FUSED (3 * EE)        // 3072

// ---------------- Scratch (static device globals) ---------------------------
__device__ __nv_bfloat16 g_xhi[(size_t)M_ROWS * EE];
__device__ __nv_bfloat16 g_xlo[(size_t)M_ROWS * EE];
__device__ __nv_bfloat16 g_Wchi[(size_t)N_FUSED * EE];
__device__ __nv_bfloat16 g_Wclo[(size_t)N_FUSED * EE];
__device__ float         g_fused[(size_t)M_ROWS * N_FUSED];   // q'|k'|v fp32
__device__ __nv_bfloat16 g_ahi[(size_t)M_ROWS * EE];
__device__ __nv_bfloat16 g_alo[(size_t)M_ROWS * EE];
__device__ __nv_bfloat16 g_wohi[(size_t)EE * EE];
__device__ __nv_bfloat16 g_wolo[(size_t)EE * EE];
__device__ float         g_kv[(size_t)HH * BB * PP * DD];
__device__ float         g_ksum[(size_t)HH * BB * PP];

// ---------------- helpers ----------------------------------------------------
__device__ __forceinline__ uint32_t smem_u32(const void* p) {
    uint32_t a;
    asm("{ .reg .u64 t; cvta.to.shared.u64 t, %1; cvt.u32.u64 %0, t; }"
        : "=r"(a) : "l"(p));
    return a;
}
__device__ __forceinline__ void cp16(uint32_t dst, const void* src) {
    asm volatile("cp.async.ca.shared.global [%0], [%1], 16;"
                 :: "r"(dst), "l"(src) : "memory");
}
#define CP_COMMIT() asm volatile("cp.async.commit_group;" ::: "memory")
#define CP_WAIT1()  asm volatile("cp.async.wait_group 1;" ::: "memory")

__device__ __forceinline__ void mma_bf16(float* c, const uint32_t* a, const uint32_t* b) {
    asm volatile(
        "mma.sync.aligned.m16n8k16.row.col.f32.bf16.bf16.f32 "
        "{%0,%1,%2,%3}, {%4,%5,%6,%7}, {%8,%9}, {%0,%1,%2,%3};"
        : "+f"(c[0]), "+f"(c[1]), "+f"(c[2]), "+f"(c[3])
        : "r"(a[0]), "r"(a[1]), "r"(a[2]), "r"(a[3]), "r"(b[0]), "r"(b[1]));
}

__device__ __forceinline__ void split1(float a, __nv_bfloat16& h, __nv_bfloat16& l) {
    h = __float2bfloat16(a);
    l = __float2bfloat16(a - __bfloat162float(h));
}
__device__ __forceinline__ void split2(float a, float b, uint32_t& hi, uint32_t& lo) {
    __nv_bfloat162 h = __floats2bfloat162_rn(a, b);
    float ra = a - __bfloat162float(h.x);
    float rb = b - __bfloat162float(h.y);
    __nv_bfloat162 l = __floats2bfloat162_rn(ra, rb);
    hi = *reinterpret_cast<uint32_t*>(&h);
    lo = *reinterpret_cast<uint32_t*>(&l);
}

// ---------------- fp32 -> (hi, lo) bf16 ---------------------------------------
__global__ void convert_kernel(const float* __restrict__ src,
                               __nv_bfloat16* __restrict__ hi,
                               __nv_bfloat16* __restrict__ lo, int n4) {
    int i = blockIdx.x * 256 + threadIdx.x;
    if (i >= n4) return;
    float4 v = reinterpret_cast<const float4*>(src)[i];
    uint32_t h0, l0, h1, l1;
    split2(v.x, v.y, h0, l0);
    split2(v.z, v.w, h1, l1);
    uint2 H; H.x = h0; H.y = h1;
    uint2 L; L.x = l0; L.y = l1;
    reinterpret_cast<uint2*>(hi)[i] = H;
    reinterpret_cast<uint2*>(lo)[i] = L;
}

// ---------------- build combined weights (hi/lo bf16) -------------------------
__global__ void build_wc_kernel(const float* __restrict__ w_qkv,
                                const float* __restrict__ w_f) {
    int n = blockIdx.x;
    int tid = threadIdx.x;   // 256
    if (n >= 2048) {
        for (int e = tid; e < EE; e += 256) {
            float v = w_qkv[(size_t)n * EE + e];
            __nv_bfloat16 h, l; split1(v, h, l);
            g_Wchi[(size_t)n * EE + e] = h;
            g_Wclo[(size_t)n * EE + e] = l;
        }
        return;
    }
    int part = n >> 10;
    int h = (n & 1023) >> 6;
    int p = n & 63;
    __shared__ float wf[64];
    if (tid < 64) wf[tid] = w_f[p * 64 + tid];
    __syncthreads();
    float acc[4] = {0.f, 0.f, 0.f, 0.f};
    const float* src = w_qkv + (size_t)(part * 1024 + h * 64) * EE;
#pragma unroll 4
    for (int d = 0; d < 64; d++) {
        float w = wf[d];
#pragma unroll
        for (int i = 0; i < 4; i++)
            acc[i] += w * src[(size_t)d * EE + tid + i * 256];
    }
#pragma unroll
    for (int i = 0; i < 4; i++) {
        size_t idx = (size_t)n * EE + tid + i * 256;
        __nv_bfloat16 hh, ll; split1(acc[i], hh, ll);
        g_Wchi[idx] = hh;
        g_Wclo[idx] = ll;
    }
}

// ---------------- HMMA split-bf16 GEMM -----------------------------------------
// C[M,N] = A[M,K]*B[N,K]^T via Ahi*Bhi + Ahi*Blo + Alo*Bhi, fp32 accum.
// 128x128 tile, BK=32, 256 thr (2x4 warps, 64x32 warp tiles), 2-stage cp.async.
// SMEM per stage: 4 operand-halves x 128 rows x 20 words (16 data + 4 pad).
// EPI 1: n<2048 -> relu(v+bias[n&63])   EPI 2: v + bias[n]
#define STG_W 10240            // words per stage
#define OP_W  2560             // words per operand-half
#define HG_SMEM_BYTES (2 * STG_W * 4)

template <int EPI>
__global__ void __launch_bounds__(256, 2)
hgemm_kernel(const __nv_bfloat16* __restrict__ Ahi, const __nv_bfloat16* __restrict__ Alo,
             const __nv_bfloat16* __restrict__ Bhi, const __nv_bfloat16* __restrict__ Blo,
             float* __restrict__ C, int M, int N, int K,
             const float* __restrict__ bias) {
    extern __shared__ uint32_t sm[];
    const int tid = threadIdx.x;
    const int lane = tid & 31, wid = tid >> 5;
    const int wm = wid >> 2, wn = wid & 3;      // 2 x 4 warp grid
    const int gr = lane >> 2, qc = lane & 3;
    const int m0 = blockIdx.y * 128, n0 = blockIdx.x * 128;

    const __nv_bfloat16* srcs[4];
    srcs[0] = Ahi + (size_t)m0 * K;
    srcs[1] = Alo + (size_t)m0 * K;
    srcs[2] = Bhi + (size_t)n0 * K;
    srcs[3] = Blo + (size_t)n0 * K;

    const uint32_t smb = smem_u32(sm);

    // row/chunk this thread copies (2 x 16B per operand-half)
    const int g0 = tid * 2;            // 0..510 step 2 -> rows g/4, chunk g%4
    auto issue = [&](int stage, int k0) {
#pragma unroll
        for (int op = 0; op < 4; op++) {
#pragma unroll
            for (int i = 0; i < 2; i++) {
                int g = g0 + i;
                int row = g >> 2, cc = g & 3;
                const __nv_bfloat16* s = srcs[op] + (size_t)row * K + k0 + cc * 8;
                uint32_t d = smb + (uint32_t)(stage * STG_W + op * OP_W + row * 20 + cc * 4) * 4;
                cp16(d, s);
            }
        }
        CP_COMMIT();
    };

    float acc[4][4][4];
#pragma unroll
    for (int i = 0; i < 4; i++)
#pragma unroll
        for (int j = 0; j < 4; j++)
#pragma unroll
            for (int q = 0; q < 4; q++) acc[i][j][q] = 0.f;

    const int nc = K >> 5;     // chunks of 32
    issue(0, 0);
    issue(1, 32);

    for (int ch = 0; ch < nc; ch++) {
        CP_WAIT1();
        __syncthreads();
        int s = ch & 1;
        const int sbase = s * STG_W;
#pragma unroll
        for (int ks = 0; ks < 2; ks++) {
            uint32_t a[4][4], b[4][2], bl[4][2];
            const int w0 = qc + ks * 8;
#pragma unroll
            for (int mt = 0; mt < 4; mt++) {
                int r = wm * 64 + mt * 16 + gr;
                int ix = sbase + r * 20 + w0;
                a[mt][0] = sm[ix];
                a[mt][1] = sm[ix + 160];        // +8 rows
                a[mt][2] = sm[ix + 4];
                a[mt][3] = sm[ix + 164];
            }
#pragma unroll
            for (int nt = 0; nt < 4; nt++) {
                int rn = wn * 32 + nt * 8 + gr;
                int ix = sbase + 2 * OP_W + rn * 20 + w0;
                b[nt][0]  = sm[ix];
                b[nt][1]  = sm[ix + 4];
                bl[nt][0] = sm[ix + OP_W];
                bl[nt][1] = sm[ix + OP_W + 4];
            }
#pragma unroll
            for (int mt = 0; mt < 4; mt++)
#pragma unroll
                for (int nt = 0; nt < 4; nt++)
                    mma_bf16(acc[mt][nt], a[mt], b[nt]);
#pragma unroll
            for (int mt = 0; mt < 4; mt++)
#pragma unroll
                for (int nt = 0; nt < 4; nt++)
                    mma_bf16(acc[mt][nt], a[mt], bl[nt]);
            // reload A-lo over a[]
#pragma unroll
            for (int mt = 0; mt < 4; mt++) {
                int r = wm * 64 + mt * 16 + gr;
                int ix = sbase + OP_W + r * 20 + w0;
                a[mt][0] = sm[ix];
                a[mt][1] = sm[ix + 160];
                a[mt][2] = sm[ix + 4];
                a[mt][3] = sm[ix + 164];
            }
#pragma unroll
            for (int mt = 0; mt < 4; mt++)
#pragma unroll
                for (int nt = 0; nt < 4; nt++)
                    mma_bf16(acc[mt][nt], a[mt], b[nt]);
        }
        __syncthreads();
        if (ch + 2 < nc) issue(s, (ch + 2) * 32);
        else CP_COMMIT();   // keep group count in lockstep
    }

    // Epilogue
#pragma unroll
    for (int mt = 0; mt < 4; mt++) {
#pragma unroll
        for (int nt = 0; nt < 4; nt++) {
            int row = m0 + wm * 64 + mt * 16 + gr;
            int col = n0 + wn * 32 + nt * 8 + qc * 2;
#pragma unroll
            for (int half = 0; half < 2; half++) {
                int r = row + half * 8;
                float v0 = acc[mt][nt][half * 2 + 0];
                float v1 = acc[mt][nt][half * 2 + 1];
                if (EPI == 1) {
                    if (col < 2048) {
                        v0 = fmaxf(v0 + bias[col & 63], 0.f);
                        v1 = fmaxf(v1 + bias[(col + 1) & 63], 0.f);
                    }
                } else if (EPI == 2) {
                    v0 += bias[col];
                    v1 += bias[col + 1];
                }
                float2 o; o.x = v0; o.y = v1;
                *reinterpret_cast<float2*>(C + (size_t)r * N + col) = o;
            }
        }
    }
}

// ---------------- Zero kv / ksum ---------------------------------------------
__global__ void zero_kernel() {
    int idx = blockIdx.x * 256 + threadIdx.x;
    const int NKV = HH * BB * PP * DD;
    if (idx < NKV) g_kv[idx] = 0.f;
    else {
        int j = idx - NKV;
        if (j < HH * BB * PP) g_ksum[j] = 0.f;
    }
}

// ---------------- kv reduction (split-S x 8) -----------------------------------
__global__ void __launch_bounds__(256)
kv_kernel() {
    int hb = blockIdx.x;
    int split = blockIdx.y;
    int h = hb >> 3, b = hb & 7;

    __shared__ float kt[64][64];
    __shared__ float vt[64][64];

    int tid = threadIdx.x;
    int c4 = tid & 15;
    int r0 = tid >> 4;

    const float* kbase = g_fused + (size_t)b * N_FUSED + 1024 + h * 64;
    const float* vbase = g_fused + (size_t)b * N_FUSED + 2048 + h * 64;

    float acc[4][4];
#pragma unroll
    for (int i = 0; i < 4; i++)
#pragma unroll
        for (int j = 0; j < 4; j++) acc[i][j] = 0.f;
    float ksacc[4] = {0.f, 0.f, 0.f, 0.f};

    int ty = tid >> 4, tx = tid & 15;
    int sbeg = split * 512;
    for (int s0 = sbeg; s0 < sbeg + 512; s0 += 64) {
#pragma unroll
        for (int i = 0; i < 4; i++) {
            int row = r0 + i * 16;
            size_t g = (size_t)(s0 + row) * BB * N_FUSED;
            float4 kval = *(const float4*)(kbase + g + c4 * 4);
            *(float4*)&kt[row][c4 * 4] = kval;
            ksacc[0] += kval.x; ksacc[1] += kval.y;
            ksacc[2] += kval.z; ksacc[3] += kval.w;
            *(float4*)&vt[row][c4 * 4] = *(const float4*)(vbase + g + c4 * 4);
        }
        __syncthreads();
#pragma unroll 8
        for (int ss = 0; ss < 64; ss++) {
            float4 a = *(const float4*)&kt[ss][ty * 4];
            float4 c = *(const float4*)&vt[ss][tx * 4];
            float av[4] = {a.x, a.y, a.z, a.w};
            float cv[4] = {c.x, c.y, c.z, c.w};
#pragma unroll
            for (int i = 0; i < 4; i++)
#pragma unroll
                for (int j = 0; j < 4; j++)
                    acc[i][j] += av[i] * cv[j];
        }
        __syncthreads();
    }

    float* kvb = g_kv + (size_t)hb * (PP * DD);
#pragma unroll
    for (int i = 0; i < 4; i++)
#pragma unroll
        for (int j = 0; j < 4; j++)
            atomicAdd(&kvb[(ty * 4 + i) * 64 + tx * 4 + j], acc[i][j]);
#pragma unroll
    for (int l = 0; l < 4; l++)
        atomicAdd(&g_ksum[hb * 64 + c4 * 4 + l], ksacc[l]);
}

// ---------------- attention + normalization (emits hi/lo bf16) ------------------
__global__ void __launch_bounds__(256)
attn_kernel() {
    int chunk = blockIdx.x;
    int hb = blockIdx.y;
    int h = hb >> 3, b = hb & 7;

    __shared__ float kvs[64][64];
    __shared__ float kss[64];
    __shared__ float qs[4][64];

    int tid = threadIdx.x;
    for (int i = tid; i < 4096; i += 256)
        kvs[i >> 6][i & 63] = g_kv[(size_t)hb * 4096 + i];
    if (tid < 64) kss[tid] = g_ksum[hb * 64 + tid];
    __syncthreads();

    int g = tid >> 6;
    int d = tid & 63;

    for (int it = 0; it < 32; it++) {
        int s = chunk * 128 + it * 4 + g;
        size_t row = ((size_t)s * BB + b) * N_FUSED;
        qs[g][d] = g_fused[row + h * 64 + d];
        __syncthreads();
        float num = 0.f, den = 0.f;
#pragma unroll
        for (int p = 0; p < 64; p++) {
            float q = qs[g][p];
            num += q * kvs[p][d];
            den += q * kss[p];
        }
        float v = num / (den + 1e-8f);
        size_t oidx = ((size_t)s * BB + b) * EE + h * 64 + d;
        __nv_bfloat16 hh, ll; split1(v, hh, ll);
        g_ahi[oidx] = hh;
        g_alo[oidx] = ll;
        __syncthreads();
    }
}

// ---------------- Launch -------------------------------------------------------
extern "C" void kernel_launch(void* const* d_in, const int* in_sizes, int n_in,
                              void* d_out, int out_size) {
    const float* x      = (const float*)d_in[0];
    const float* w_qkv  = (const float*)d_in[1];
    const float* w_out  = (const float*)d_in[2];
    const float* b_out  = (const float*)d_in[3];
    const float* w_f    = (const float*)d_in[4];
    const float* b_f    = (const float*)d_in[5];
    float* out = (float*)d_out;

    __nv_bfloat16 *xhi, *xlo, *wchi, *wclo, *ahi, *alo, *wohi, *wolo;
    float *fused_p;
    cudaGetSymbolAddress((void**)&xhi, g_xhi);
    cudaGetSymbolAddress((void**)&xlo, g_xlo);
    cudaGetSymbolAddress((void**)&wchi, g_Wchi);
    cudaGetSymbolAddress((void**)&wclo, g_Wclo);
    cudaGetSymbolAddress((void**)&ahi, g_ahi);
    cudaGetSymbolAddress((void**)&alo, g_alo);
    cudaGetSymbolAddress((void**)&wohi, g_wohi);
    cudaGetSymbolAddress((void**)&wolo, g_wolo);
    cudaGetSymbolAddress((void**)&fused_p, g_fused);

    cudaFuncSetAttribute(hgemm_kernel<1>, cudaFuncAttributeMaxDynamicSharedMemorySize, HG_SMEM_BYTES);
    cudaFuncSetAttribute(hgemm_kernel<2>, cudaFuncAttributeMaxDynamicSharedMemorySize, HG_SMEM_BYTES);

    // 1. combined weights (hi/lo) + conversions
    build_wc_kernel<<<N_FUSED, 256>>>(w_qkv, w_f);
    convert_kernel<<<(M_ROWS * EE / 4 + 255) / 256, 256>>>(x, xhi, xlo, M_ROWS * EE / 4);
    convert_kernel<<<(EE * EE / 4 + 255) / 256, 256>>>(w_out, wohi, wolo, EE * EE / 4);

    // 2. fused qkv+featuremap GEMM (HMMA split-bf16)
    hgemm_kernel<1><<<dim3(N_FUSED / 128, M_ROWS / 128), 256, HG_SMEM_BYTES>>>(
        xhi, xlo, wchi, wclo, fused_p, M_ROWS, N_FUSED, EE, b_f);

    // 3. zero accumulators
    zero_kernel<<<(HH * BB * PP * DD + HH * BB * PP + 255) / 256, 256>>>();

    // 4. kv / ksum reduction
    kv_kernel<<<dim3(HH * BB, 8), 256>>>();

    // 5. attention + normalization
    attn_kernel<<<dim3(SS / 128, HH * BB), 256>>>();

    // 6. output projection (HMMA split-bf16)
    hgemm_kernel<2><<<dim3(EE / 128, M_ROWS / 128), 256, HG_SMEM_BYTES>>>(
        ahi, alo, wohi, wolo, out, M_ROWS, EE, EE, b_out);
}

// round 4
// speedup vs baseline: 2.1900x; 1.1823x over previous
#include <cuda_runtime.h>
#include <cuda_bf16.h>
#include <cstdint>

// Problem constants
#define SS 4096
#define BB 8
#define EE 1024
#define HH 16
#define DD 64
#define PP 64
#define M_ROWS (SS * BB)        // 32768
#define N_FUSED (3 * EE)        // 3072

// ---------------- Scratch (static device globals) ---------------------------
__device__ __nv_bfloat16 g_xhi[(size_t)M_ROWS * EE];
__device__ __nv_bfloat16 g_xlo[(size_t)M_ROWS * EE];
__device__ __nv_bfloat16 g_Wchi[(size_t)N_FUSED * EE];
__device__ __nv_bfloat16 g_Wclo[(size_t)N_FUSED * EE];
__device__ float         g_fused[(size_t)M_ROWS * N_FUSED];   // q'|k'|v fp32
__device__ __nv_bfloat16 g_ahi[(size_t)M_ROWS * EE];
__device__ __nv_bfloat16 g_alo[(size_t)M_ROWS * EE];
__device__ __nv_bfloat16 g_wohi[(size_t)EE * EE];
__device__ __nv_bfloat16 g_wolo[(size_t)EE * EE];
__device__ float         g_kv[(size_t)HH * BB * PP * DD];
__device__ float         g_ksum[(size_t)HH * BB * PP];

// ---------------- helpers ----------------------------------------------------
__device__ __forceinline__ uint32_t smem_u32(const void* p) {
    uint32_t a;
    asm("{ .reg .u64 t; cvta.to.shared.u64 t, %1; cvt.u32.u64 %0, t; }"
        : "=r"(a) : "l"(p));
    return a;
}
__device__ __forceinline__ void cp16(uint32_t dst, const void* src) {
    asm volatile("cp.async.ca.shared.global [%0], [%1], 16;"
                 :: "r"(dst), "l"(src) : "memory");
}
#define CP_COMMIT() asm volatile("cp.async.commit_group;" ::: "memory")
#define CP_WAIT1()  asm volatile("cp.async.wait_group 1;" ::: "memory")

#define LDM4(r0, r1, r2, r3, addr) \
    asm volatile("ldmatrix.sync.aligned.m8n8.x4.shared.b16 {%0,%1,%2,%3}, [%4];" \
                 : "=r"(r0), "=r"(r1), "=r"(r2), "=r"(r3) : "r"(addr))

__device__ __forceinline__ void mma_bf16(float* c, const uint32_t* a, const uint32_t* b) {
    asm volatile(
        "mma.sync.aligned.m16n8k16.row.col.f32.bf16.bf16.f32 "
        "{%0,%1,%2,%3}, {%4,%5,%6,%7}, {%8,%9}, {%0,%1,%2,%3};"
        : "+f"(c[0]), "+f"(c[1]), "+f"(c[2]), "+f"(c[3])
        : "r"(a[0]), "r"(a[1]), "r"(a[2]), "r"(a[3]), "r"(b[0]), "r"(b[1]));
}

__device__ __forceinline__ void split1(float a, __nv_bfloat16& h, __nv_bfloat16& l) {
    h = __float2bfloat16(a);
    l = __float2bfloat16(a - __bfloat162float(h));
}
__device__ __forceinline__ void split2(float a, float b, uint32_t& hi, uint32_t& lo) {
    __nv_bfloat162 h = __floats2bfloat162_rn(a, b);
    float ra = a - __bfloat162float(h.x);
    float rb = b - __bfloat162float(h.y);
    __nv_bfloat162 l = __floats2bfloat162_rn(ra, rb);
    hi = *reinterpret_cast<uint32_t*>(&h);
    lo = *reinterpret_cast<uint32_t*>(&l);
}

// ---------------- fp32 -> (hi, lo) bf16 ---------------------------------------
__global__ void convert_kernel(const float* __restrict__ src,
                               __nv_bfloat16* __restrict__ hi,
                               __nv_bfloat16* __restrict__ lo, int n4) {
    int i = blockIdx.x * 256 + threadIdx.x;
    if (i >= n4) return;
    float4 v = reinterpret_cast<const float4*>(src)[i];
    uint32_t h0, l0, h1, l1;
    split2(v.x, v.y, h0, l0);
    split2(v.z, v.w, h1, l1);
    uint2 H; H.x = h0; H.y = h1;
    uint2 L; L.x = l0; L.y = l1;
    reinterpret_cast<uint2*>(hi)[i] = H;
    reinterpret_cast<uint2*>(lo)[i] = L;
}

// ---------------- build combined weights (hi/lo bf16) -------------------------
__global__ void build_wc_kernel(const float* __restrict__ w_qkv,
                                const float* __restrict__ w_f) {
    int n = blockIdx.x;
    int tid = threadIdx.x;   // 256
    if (n >= 2048) {
        for (int e = tid; e < EE; e += 256) {
            float v = w_qkv[(size_t)n * EE + e];
            __nv_bfloat16 h, l; split1(v, h, l);
            g_Wchi[(size_t)n * EE + e] = h;
            g_Wclo[(size_t)n * EE + e] = l;
        }
        return;
    }
    int part = n >> 10;
    int h = (n & 1023) >> 6;
    int p = n & 63;
    __shared__ float wf[64];
    if (tid < 64) wf[tid] = w_f[p * 64 + tid];
    __syncthreads();
    float acc[4] = {0.f, 0.f, 0.f, 0.f};
    const float* src = w_qkv + (size_t)(part * 1024 + h * 64) * EE;
#pragma unroll 4
    for (int d = 0; d < 64; d++) {
        float w = wf[d];
#pragma unroll
        for (int i = 0; i < 4; i++)
            acc[i] += w * src[(size_t)d * EE + tid + i * 256];
    }
#pragma unroll
    for (int i = 0; i < 4; i++) {
        size_t idx = (size_t)n * EE + tid + i * 256;
        __nv_bfloat16 hh, ll; split1(acc[i], hh, ll);
        g_Wchi[idx] = hh;
        g_Wclo[idx] = ll;
    }
}

// ---------------- HMMA split-bf16 GEMM (ldmatrix fragments) --------------------
// C[M,N] = A[M,K]*B[N,K]^T via Ahi*Bhi + Ahi*Blo + Alo*Bhi, fp32 accum.
// 128x128 tile, BK=32, 256 thr (2x4 warps, 64x32 warp tiles), 2-stage cp.async.
// SMEM per stage: 4 operand-halves x 128 rows x 20 words (16 data + 4 pad).
#define STG_W 10240            // words per stage
#define OP_W  2560             // words per operand-half
#define HG_SMEM_BYTES (2 * STG_W * 4)

template <int EPI>
__global__ void __launch_bounds__(256, 2)
hgemm_kernel(const __nv_bfloat16* __restrict__ Ahi, const __nv_bfloat16* __restrict__ Alo,
             const __nv_bfloat16* __restrict__ Bhi, const __nv_bfloat16* __restrict__ Blo,
             float* __restrict__ C, int M, int N, int K,
             const float* __restrict__ bias) {
    extern __shared__ uint32_t sm[];
    const int tid = threadIdx.x;
    const int lane = tid & 31, wid = tid >> 5;
    const int wm = wid >> 2, wn = wid & 3;      // 2 x 4 warp grid
    const int gr = lane >> 2, qc = lane & 3;
    const int m0 = blockIdx.y * 128, n0 = blockIdx.x * 128;

    const __nv_bfloat16* srcs[4];
    srcs[0] = Ahi + (size_t)m0 * K;
    srcs[1] = Alo + (size_t)m0 * K;
    srcs[2] = Bhi + (size_t)n0 * K;
    srcs[3] = Blo + (size_t)n0 * K;

    const uint32_t smb = smem_u32(sm);

    // ldmatrix per-thread address components (byte offsets within a stage)
    // A tile (mt): rows wm*64 + mt*16 + (lane&15); +16B column for lane>=16
    const uint32_t a_base = smb + (uint32_t)(wm * 64 + (lane & 15)) * 80 + (lane >> 4) * 16;
    // B tile-pair (p): rows wn*32 + p*16 + (lane>>4)*8 + (lane&7); k-block by bit3
    const uint32_t b_row = (uint32_t)(wn * 32 + ((lane >> 4) << 3) + (lane & 7));
    const uint32_t b_base = smb + b_row * 80 + ((lane >> 3) & 1) * 16;

    // cp.async: row/chunk this thread copies (2 x 16B per operand-half)
    const int g0 = tid * 2;
    auto issue = [&](int stage, int k0) {
#pragma unroll
        for (int op = 0; op < 4; op++) {
#pragma unroll
            for (int i = 0; i < 2; i++) {
                int g = g0 + i;
                int row = g >> 2, cc = g & 3;
                const __nv_bfloat16* s = srcs[op] + (size_t)row * K + k0 + cc * 8;
                uint32_t d = smb + (uint32_t)(stage * STG_W + op * OP_W + row * 20 + cc * 4) * 4;
                cp16(d, s);
            }
        }
        CP_COMMIT();
    };

    float acc[4][4][4];
#pragma unroll
    for (int i = 0; i < 4; i++)
#pragma unroll
        for (int j = 0; j < 4; j++)
#pragma unroll
            for (int q = 0; q < 4; q++) acc[i][j][q] = 0.f;

    const int nc = K >> 5;     // chunks of 32
    issue(0, 0);
    issue(1, 32);

    for (int ch = 0; ch < nc; ch++) {
        CP_WAIT1();
        __syncthreads();
        int s = ch & 1;
        const uint32_t sb4 = (uint32_t)(s * STG_W) * 4;   // stage byte offset
#pragma unroll
        for (int ks = 0; ks < 2; ks++) {
            const uint32_t kb = ks * 32;
            uint32_t a[4][4], b[4][2], bl[4][2];
            // B hi (two x4 = all 4 n-tiles)
#pragma unroll
            for (int p = 0; p < 2; p++) {
                uint32_t ad = b_base + sb4 + (uint32_t)(2 * OP_W) * 4 + (uint32_t)p * 16 * 80 + kb;
                LDM4(b[2 * p][0], b[2 * p][1], b[2 * p + 1][0], b[2 * p + 1][1], ad);
            }
            // B lo
#pragma unroll
            for (int p = 0; p < 2; p++) {
                uint32_t ad = b_base + sb4 + (uint32_t)(3 * OP_W) * 4 + (uint32_t)p * 16 * 80 + kb;
                LDM4(bl[2 * p][0], bl[2 * p][1], bl[2 * p + 1][0], bl[2 * p + 1][1], ad);
            }
            // A hi
#pragma unroll
            for (int mt = 0; mt < 4; mt++) {
                uint32_t ad = a_base + sb4 + (uint32_t)mt * 16 * 80 + kb;
                LDM4(a[mt][0], a[mt][1], a[mt][2], a[mt][3], ad);
            }
#pragma unroll
            for (int mt = 0; mt < 4; mt++)
#pragma unroll
                for (int nt = 0; nt < 4; nt++)
                    mma_bf16(acc[mt][nt], a[mt], b[nt]);
#pragma unroll
            for (int mt = 0; mt < 4; mt++)
#pragma unroll
                for (int nt = 0; nt < 4; nt++)
                    mma_bf16(acc[mt][nt], a[mt], bl[nt]);
            // A lo (reuse a[] registers)
#pragma unroll
            for (int mt = 0; mt < 4; mt++) {
                uint32_t ad = a_base + sb4 + (uint32_t)OP_W * 4 + (uint32_t)mt * 16 * 80 + kb;
                LDM4(a[mt][0], a[mt][1], a[mt][2], a[mt][3], ad);
            }
#pragma unroll
            for (int mt = 0; mt < 4; mt++)
#pragma unroll
                for (int nt = 0; nt < 4; nt++)
                    mma_bf16(acc[mt][nt], a[mt], b[nt]);
        }
        __syncthreads();
        if (ch + 2 < nc) issue(s, (ch + 2) * 32);
        else CP_COMMIT();   // keep group count in lockstep
    }

    // Epilogue
#pragma unroll
    for (int mt = 0; mt < 4; mt++) {
#pragma unroll
        for (int nt = 0; nt < 4; nt++) {
            int row = m0 + wm * 64 + mt * 16 + gr;
            int col = n0 + wn * 32 + nt * 8 + qc * 2;
#pragma unroll
            for (int half = 0; half < 2; half++) {
                int r = row + half * 8;
                float v0 = acc[mt][nt][half * 2 + 0];
                float v1 = acc[mt][nt][half * 2 + 1];
                if (EPI == 1) {
                    if (col < 2048) {
                        v0 = fmaxf(v0 + bias[col & 63], 0.f);
                        v1 = fmaxf(v1 + bias[(col + 1) & 63], 0.f);
                    }
                } else if (EPI == 2) {
                    v0 += bias[col];
                    v1 += bias[col + 1];
                }
                float2 o; o.x = v0; o.y = v1;
                *reinterpret_cast<float2*>(C + (size_t)r * N + col) = o;
            }
        }
    }
}

// ---------------- Zero kv / ksum ---------------------------------------------
__global__ void zero_kernel() {
    int idx = blockIdx.x * 256 + threadIdx.x;
    const int NKV = HH * BB * PP * DD;
    if (idx < NKV) g_kv[idx] = 0.f;
    else {
        int j = idx - NKV;
        if (j < HH * BB * PP) g_ksum[j] = 0.f;
    }
}

// ---------------- kv reduction (split-S x 8) -----------------------------------
__global__ void __launch_bounds__(256)
kv_kernel() {
    int hb = blockIdx.x;
    int split = blockIdx.y;
    int h = hb >> 3, b = hb & 7;

    __shared__ float kt[64][64];
    __shared__ float vt[64][64];

    int tid = threadIdx.x;
    int c4 = tid & 15;
    int r0 = tid >> 4;

    const float* kbase = g_fused + (size_t)b * N_FUSED + 1024 + h * 64;
    const float* vbase = g_fused + (size_t)b * N_FUSED + 2048 + h * 64;

    float acc[4][4];
#pragma unroll
    for (int i = 0; i < 4; i++)
#pragma unroll
        for (int j = 0; j < 4; j++) acc[i][j] = 0.f;
    float ksacc[4] = {0.f, 0.f, 0.f, 0.f};

    int ty = tid >> 4, tx = tid & 15;
    int sbeg = split * 512;
    for (int s0 = sbeg; s0 < sbeg + 512; s0 += 64) {
#pragma unroll
        for (int i = 0; i < 4; i++) {
            int row = r0 + i * 16;
            size_t g = (size_t)(s0 + row) * BB * N_FUSED;
            float4 kval = *(const float4*)(kbase + g + c4 * 4);
            *(float4*)&kt[row][c4 * 4] = kval;
            ksacc[0] += kval.x; ksacc[1] += kval.y;
            ksacc[2] += kval.z; ksacc[3] += kval.w;
            *(float4*)&vt[row][c4 * 4] = *(const float4*)(vbase + g + c4 * 4);
        }
        __syncthreads();
#pragma unroll 8
        for (int ss = 0; ss < 64; ss++) {
            float4 a = *(const float4*)&kt[ss][ty * 4];
            float4 c = *(const float4*)&vt[ss][tx * 4];
            float av[4] = {a.x, a.y, a.z, a.w};
            float cv[4] = {c.x, c.y, c.z, c.w};
#pragma unroll
            for (int i = 0; i < 4; i++)
#pragma unroll
                for (int j = 0; j < 4; j++)
                    acc[i][j] += av[i] * cv[j];
        }
        __syncthreads();
    }

    float* kvb = g_kv + (size_t)hb * (PP * DD);
#pragma unroll
    for (int i = 0; i < 4; i++)
#pragma unroll
        for (int j = 0; j < 4; j++)
            atomicAdd(&kvb[(ty * 4 + i) * 64 + tx * 4 + j], acc[i][j]);
#pragma unroll
    for (int l = 0; l < 4; l++)
        atomicAdd(&g_ksum[hb * 64 + c4 * 4 + l], ksacc[l]);
}

// ---------------- attention + normalization (emits hi/lo bf16) ------------------
__global__ void __launch_bounds__(256)
attn_kernel() {
    int chunk = blockIdx.x;
    int hb = blockIdx.y;
    int h = hb >> 3, b = hb & 7;

    __shared__ float kvs[64][64];
    __shared__ float kss[64];
    __shared__ float qs[4][64];

    int tid = threadIdx.x;
    for (int i = tid; i < 4096; i += 256)
        kvs[i >> 6][i & 63] = g_kv[(size_t)hb * 4096 + i];
    if (tid < 64) kss[tid] = g_ksum[hb * 64 + tid];
    __syncthreads();

    int g = tid >> 6;
    int d = tid & 63;

    for (int it = 0; it < 32; it++) {
        int s = chunk * 128 + it * 4 + g;
        size_t row = ((size_t)s * BB + b) * N_FUSED;
        qs[g][d] = g_fused[row + h * 64 + d];
        __syncthreads();
        float num = 0.f, den = 0.f;
#pragma unroll
        for (int p = 0; p < 64; p++) {
            float q = qs[g][p];
            num += q * kvs[p][d];
            den += q * kss[p];
        }
        float v = num / (den + 1e-8f);
        size_t oidx = ((size_t)s * BB + b) * EE + h * 64 + d;
        __nv_bfloat16 hh, ll; split1(v, hh, ll);
        g_ahi[oidx] = hh;
        g_alo[oidx] = ll;
        __syncthreads();
    }
}

// ---------------- Launch -------------------------------------------------------
extern "C" void kernel_launch(void* const* d_in, const int* in_sizes, int n_in,
                              void* d_out, int out_size) {
    const float* x      = (const float*)d_in[0];
    const float* w_qkv  = (const float*)d_in[1];
    const float* w_out  = (const float*)d_in[2];
    const float* b_out  = (const float*)d_in[3];
    const float* w_f    = (const float*)d_in[4];
    const float* b_f    = (const float*)d_in[5];
    float* out = (float*)d_out;

    __nv_bfloat16 *xhi, *xlo, *wchi, *wclo, *ahi, *alo, *wohi, *wolo;
    float *fused_p;
    cudaGetSymbolAddress((void**)&xhi, g_xhi);
    cudaGetSymbolAddress((void**)&xlo, g_xlo);
    cudaGetSymbolAddress((void**)&wchi, g_Wchi);
    cudaGetSymbolAddress((void**)&wclo, g_Wclo);
    cudaGetSymbolAddress((void**)&ahi, g_ahi);
    cudaGetSymbolAddress((void**)&alo, g_alo);
    cudaGetSymbolAddress((void**)&wohi, g_wohi);
    cudaGetSymbolAddress((void**)&wolo, g_wolo);
    cudaGetSymbolAddress((void**)&fused_p, g_fused);

    cudaFuncSetAttribute(hgemm_kernel<1>, cudaFuncAttributeMaxDynamicSharedMemorySize, HG_SMEM_BYTES);
    cudaFuncSetAttribute(hgemm_kernel<2>, cudaFuncAttributeMaxDynamicSharedMemorySize, HG_SMEM_BYTES);

    // 1. combined weights (hi/lo) + conversions
    build_wc_kernel<<<N_FUSED, 256>>>(w_qkv, w_f);
    convert_kernel<<<(M_ROWS * EE / 4 + 255) / 256, 256>>>(x, xhi, xlo, M_ROWS * EE / 4);
    convert_kernel<<<(EE * EE / 4 + 255) / 256, 256>>>(w_out, wohi, wolo, EE * EE / 4);

    // 2. fused qkv+featuremap GEMM (HMMA split-bf16)
    hgemm_kernel<1><<<dim3(N_FUSED / 128, M_ROWS / 128), 256, HG_SMEM_BYTES>>>(
        xhi, xlo, wchi, wclo, fused_p, M_ROWS, N_FUSED, EE, b_f);

    // 3. zero accumulators
    zero_kernel<<<(HH * BB * PP * DD + HH * BB * PP + 255) / 256, 256>>>();

    // 4. kv / ksum reduction
    kv_kernel<<<dim3(HH * BB, 8), 256>>>();

    // 5. attention + normalization
    attn_kernel<<<dim3(SS / 128, HH * BB), 256>>>();

    // 6. output projection (HMMA split-bf16)
    hgemm_kernel<2><<<dim3(EE / 128, M_ROWS / 128), 256, HG_SMEM_BYTES>>>(
        ahi, alo, wohi, wolo, out, M_ROWS, EE, EE, b_out);
}